// round 14
// baseline (speedup 1.0000x reference)
#include <cuda_runtime.h>
#include <cuda_fp16.h>
#include <cstdint>

#define NN   50000
#define EE   800000
#define DIN  128
#define HH   64
#define AB   6250                 // agg blocks: 8 rows x 6250 = 50000 exactly
#define CW   64                   // CSR bucket capacity per node (max deg ~35)
#define GTB  391                  // gemm tile blocks: 391 x 128 rows >= NN

// ---------------- scratch (static device globals: no allocation) -------------
// NOTE: device globals are zero-initialized at module load. g_cur is re-zeroed
// by finish_kernel at the end of every launch, so each call starts clean.
__device__ int    g_cur[NN];                 // per-node cursor (zeroed each call)
__device__ int    g_deg[NN];                 // capped degree
__device__ float  g_dinv[NN];
__device__ int    g_rank[EE];                // edge rank within dst bucket
__device__ int    g_col[(size_t)NN * CW];    // bucketed CSR; pads = NN (dummy)
__device__ __align__(16) __half g_xh[(size_t)NN * DIN];      // fp16 x
__device__ __align__(16) __half g_w1t[HH * DIN];             // W1^T [64][128] fp16
__device__ __align__(16) __half g_w2t[HH * HH];              // W2^T [64][64]
__device__ __align__(16) __half g_w3t[HH * HH];              // W3^T [64][64]
__device__ __align__(16) __half g_hH[(size_t)(NN + 1) * HH]; // gemm out: dinv*h fp16; row NN stays 0
__device__ __align__(16) __half g_hAH[(size_t)NN * HH];      // agg out fp16 (gemm2/3 input)
__device__ float2 g_psT[32 * AB];            // pool sum partials [lanecol][blk]
__device__ float2 g_pmT[32 * AB];            // pool max partials
__device__ float  g_poolS[HH];
__device__ float  g_poolM[HH];

// ---------------- PDL + PTX helpers ------------------------------------------
// no-ops when the launch has no programmatic dependency configured
#define PDL_LAUNCH_DEPENDENTS() asm volatile("griddepcontrol.launch_dependents;")
#define PDL_WAIT()              asm volatile("griddepcontrol.wait;" ::: "memory")

__device__ __forceinline__ uint32_t smem_u32(const void* p) {
    uint32_t a;
    asm("{ .reg .u64 t; cvta.to.shared.u64 t, %1; cvt.u32.u64 %0, t; }"
        : "=r"(a) : "l"(p));
    return a;
}
__device__ __forceinline__ void ldsm4(uint32_t* r, uint32_t addr) {
    asm volatile("ldmatrix.sync.aligned.m8n8.x4.shared.b16 {%0,%1,%2,%3}, [%4];"
                 : "=r"(r[0]), "=r"(r[1]), "=r"(r[2]), "=r"(r[3]) : "r"(addr));
}
__device__ __forceinline__ void mma16816(float* c, const uint32_t* a,
                                         uint32_t b0, uint32_t b1) {
    asm volatile(
        "mma.sync.aligned.m16n8k16.row.col.f32.f16.f16.f32 "
        "{%0,%1,%2,%3}, {%4,%5,%6,%7}, {%8,%9}, {%0,%1,%2,%3};"
        : "+f"(c[0]), "+f"(c[1]), "+f"(c[2]), "+f"(c[3])
        : "r"(a[0]), "r"(a[1]), "r"(a[2]), "r"(a[3]), "r"(b0), "r"(b1));
}

// ---------------- CSR build ----------------------------------------------------
// histogram, 8 edges/thread; atomic return value = edge rank in dst bucket
__global__ void count_kernel(const int* __restrict__ ei) {
    PDL_LAUNCH_DEPENDENTS();
    int i = blockIdx.x * blockDim.x + threadIdx.x;
    if (i >= EE / 8) return;
    int4 da = reinterpret_cast<const int4*>(ei + EE)[2 * i];
    int4 db = reinterpret_cast<const int4*>(ei + EE)[2 * i + 1];
    int4 ra, rb;
    ra.x = atomicAdd(&g_cur[da.x], 1);
    ra.y = atomicAdd(&g_cur[da.y], 1);
    ra.z = atomicAdd(&g_cur[da.z], 1);
    ra.w = atomicAdd(&g_cur[da.w], 1);
    rb.x = atomicAdd(&g_cur[db.x], 1);
    rb.y = atomicAdd(&g_cur[db.y], 1);
    rb.z = atomicAdd(&g_cur[db.z], 1);
    rb.w = atomicAdd(&g_cur[db.w], 1);
    reinterpret_cast<int4*>(g_rank)[2 * i]     = ra;
    reinterpret_cast<int4*>(g_rank)[2 * i + 1] = rb;
}

// dinv + capped deg + bucket pads + cursor reset (so next call starts clean)
__global__ void finish_kernel() {
    PDL_LAUNCH_DEPENDENTS();
    int i = blockIdx.x * blockDim.x + threadIdx.x;
    if (i >= NN) return;
    PDL_WAIT();
    int c = g_cur[i];
    int d = min(c, CW);
    int pd = (d + 3) & ~3;
    g_deg[i]  = d;
    g_dinv[i] = rsqrtf((float)c + 1.0f);
    for (int p = d; p < pd; p++) g_col[i * CW + p] = NN;   // pad -> dummy zero row
    g_cur[i] = 0;
}

// atomic-free scatter (8 edges/thread): slot = dst*CW + rank
__global__ void scatter_kernel(const int* __restrict__ ei) {
    PDL_LAUNCH_DEPENDENTS();
    int i = blockIdx.x * blockDim.x + threadIdx.x;
    if (i >= EE / 8) return;
    PDL_WAIT();
#pragma unroll
    for (int h = 0; h < 2; h++) {
        int4 s4 = reinterpret_cast<const int4*>(ei)[2 * i + h];
        int4 d4 = reinterpret_cast<const int4*>(ei + EE)[2 * i + h];
        int4 r4 = reinterpret_cast<const int4*>(g_rank)[2 * i + h];
        if (r4.x < CW) g_col[d4.x * CW + r4.x] = s4.x;
        if (r4.y < CW) g_col[d4.y * CW + r4.y] = s4.y;
        if (r4.z < CW) g_col[d4.z * CW + r4.z] = s4.z;
        if (r4.w < CW) g_col[d4.w * CW + r4.w] = s4.w;
    }
}

// ---------------- fp16 conversion kernels (side stream) ----------------------
__global__ void xconv_kernel(const float* __restrict__ x) {
    int i = blockIdx.x * blockDim.x + threadIdx.x;   // over float4s: NN*DIN/4
    if (i >= NN * DIN / 4) return;
    float4 v = reinterpret_cast<const float4*>(x)[i];
    __half2 a = __floats2half2_rn(v.x, v.y);
    __half2 b = __floats2half2_rn(v.z, v.w);
    uint2 o = make_uint2(*reinterpret_cast<unsigned*>(&a), *reinterpret_cast<unsigned*>(&b));
    reinterpret_cast<uint2*>(g_xh)[i] = o;
}

__global__ void wconv_kernel(const float* __restrict__ W1,
                             const float* __restrict__ W2,
                             const float* __restrict__ W3) {
    int i = blockIdx.x * blockDim.x + threadIdx.x;
    if (i < DIN * HH) {
        int k = i / HH, n = i % HH;
        g_w1t[n * DIN + k] = __float2half(W1[i]);
    } else if (i < DIN * HH + HH * HH) {
        int j = i - DIN * HH, k = j / HH, n = j % HH;
        g_w2t[n * HH + k] = __float2half(W2[j]);
    } else if (i < DIN * HH + 2 * HH * HH) {
        int j = i - DIN * HH - HH * HH, k = j / HH, n = j % HH;
        g_w3t[n * HH + k] = __float2half(W3[j]);
    }
}

// ---------------- HMMA GEMM: hH = fp16( dinv * (A[N,K] @ Bt[64,K]^T) ) -------
// Per CTA: 128 rows x 64 cols, 4 warps (warp w = rows 32w..32w+31).
// Smem padded row stride S = K+8 halves => conflict-free ldmatrix.
template <int K>
__global__ __launch_bounds__(128) void gemm_mma_kernel(const __half* __restrict__ Asrc,
                                                       const __half* __restrict__ Bt,
                                                       int nrows) {
    PDL_LAUNCH_DEPENDENTS();
    constexpr int S  = K + 8;                 // halves per smem row
    constexpr int RQ = K / 8;                 // uint4 chunks per source row
    extern __shared__ __align__(16) __half smem[];
    __half* As = smem;                        // 128 x S
    __half* Bs = smem + 128 * S;              // 64 x S
    const int tid = threadIdx.x, wid = tid >> 5, lane = tid & 31;
    const int rowbase = blockIdx.x * 128;
    PDL_WAIT();

    // fill A (guard rows past nrows with zeros)
    for (int idx = tid; idx < 128 * RQ; idx += 128) {
        int r = idx / RQ, j = idx % RQ;
        uint4 v = make_uint4(0, 0, 0, 0);
        if (rowbase + r < nrows)
            v = reinterpret_cast<const uint4*>(Asrc)[(size_t)(rowbase + r) * RQ + j];
        *reinterpret_cast<uint4*>(As + r * S + j * 8) = v;
    }
    // fill B (W^T: 64 rows x K)
    for (int idx = tid; idx < 64 * RQ; idx += 128) {
        int r = idx / RQ, j = idx % RQ;
        uint4 v = reinterpret_cast<const uint4*>(Bt)[(size_t)r * RQ + j];
        *reinterpret_cast<uint4*>(Bs + r * S + j * 8) = v;
    }
    __syncthreads();

    float acc[2][8][4];
#pragma unroll
    for (int rg = 0; rg < 2; rg++)
#pragma unroll
        for (int ng = 0; ng < 8; ng++)
#pragma unroll
            for (int q = 0; q < 4; q++) acc[rg][ng][q] = 0.f;

    const uint32_t sA = smem_u32(As), sB = smem_u32(Bs);

#pragma unroll
    for (int ks = 0; ks < K / 16; ks++) {
        uint32_t a[2][4];
#pragma unroll
        for (int rg = 0; rg < 2; rg++) {
            int row = wid * 32 + rg * 16 + (lane & 15);
            uint32_t addr = sA + (uint32_t)(row * S + ks * 16 + (lane >> 4) * 8) * 2;
            ldsm4(a[rg], addr);
        }
        uint32_t b[4][4];
#pragma unroll
        for (int np = 0; np < 4; np++) {
            int row = np * 16 + (lane & 7) + ((lane >> 4) << 3);
            int col = ks * 16 + (((lane >> 3) & 1) << 3);
            uint32_t addr = sB + (uint32_t)(row * S + col) * 2;
            ldsm4(b[np], addr);
        }
#pragma unroll
        for (int rg = 0; rg < 2; rg++)
#pragma unroll
            for (int ng = 0; ng < 8; ng++)
                mma16816(acc[rg][ng], a[rg],
                         b[ng >> 1][(ng & 1) * 2], b[ng >> 1][(ng & 1) * 2 + 1]);
    }

    // epilogue: D thread map c0,c1 -> (lane/4, 2*(lane%4)+{0,1}); c2,c3 -> row+8.
#pragma unroll
    for (int rg = 0; rg < 2; rg++) {
        int ra = rowbase + wid * 32 + rg * 16 + (lane >> 2);
        int rb = ra + 8;
        float da = (ra < nrows) ? g_dinv[ra] : 0.f;
        float db = (rb < nrows) ? g_dinv[rb] : 0.f;
#pragma unroll
        for (int ng = 0; ng < 8; ng++) {
            int col = ng * 8 + (lane & 3) * 2;
            if (ra < nrows) {
                __half2 h = __floats2half2_rn(acc[rg][ng][0] * da, acc[rg][ng][1] * da);
                *reinterpret_cast<__half2*>(g_hH + (size_t)ra * HH + col) = h;
            }
            if (rb < nrows) {
                __half2 h = __floats2half2_rn(acc[rg][ng][2] * db, acc[rg][ng][3] * db);
                *reinterpret_cast<__half2*>(g_hH + (size_t)rb * HH + col) = h;
            }
        }
    }
}

// ---------------- aggregation: warp per node, shfl-free fp16 gather ----------
// A[i] = relu( dinv_i * (sum_j h'_j + h'_i) + b ),   h' = dinv*h (fp16)
__device__ __forceinline__ float2 agg_row(int row, int lane) {
    int  deg    = g_deg[row];
    int  padded = (deg + 3) & ~3;             // pad slots index dummy zero row
    const int*      cp = g_col + row * CW;
    const unsigned* hb = reinterpret_cast<const unsigned*>(g_hH);

    float ax = 0.f, ay = 0.f;
#pragma unroll 4
    for (int p = 0; p < padded; p++) {
        int sj = __ldg(cp + p);               // warp-uniform broadcast load
        unsigned hv = __ldg(hb + sj * 32 + lane);
        float2 f = __half22float2(*reinterpret_cast<const __half2*>(&hv));
        ax += f.x;
        ay += f.y;
    }
    return make_float2(ax, ay);
}

__device__ __forceinline__ float2 agg_finish(int row, int lane, float2 a,
                                             const float* bias) {
    const unsigned* hb = reinterpret_cast<const unsigned*>(g_hH);
    unsigned hs = hb[row * 32 + lane];
    float2 fs = __half22float2(*reinterpret_cast<const __half2*>(&hs));
    float di = g_dinv[row];
    float2 b = reinterpret_cast<const float2*>(bias)[lane];
    float ox = fmaf(di, a.x + fs.x, b.x);
    float oy = fmaf(di, a.y + fs.y, b.y);
    return make_float2(fmaxf(ox, 0.f), fmaxf(oy, 0.f));
}

__global__ void agg_kernel(const float* __restrict__ bias) {
    PDL_LAUNCH_DEPENDENTS();
    int warp = threadIdx.x >> 5;
    int lane = threadIdx.x & 31;
    int row  = blockIdx.x * 8 + warp;
    PDL_WAIT();
    float2 a = agg_row(row, lane);
    float2 o = agg_finish(row, lane, a, bias);
    __half2 oh = __floats2half2_rn(o.x, o.y);
    reinterpret_cast<unsigned*>(g_hAH)[row * 32 + lane] =
        *reinterpret_cast<unsigned*>(&oh);
}

// layer-3 agg with fused pooling partials (activations never materialized)
__global__ void agg_pool_kernel(const float* __restrict__ bias) {
    PDL_LAUNCH_DEPENDENTS();
    __shared__ float2 s_sum[8][32];
    int warp = threadIdx.x >> 5;
    int lane = threadIdx.x & 31;
    int row  = blockIdx.x * 8 + warp;
    PDL_WAIT();

    float2 a = agg_row(row, lane);
    float2 o = agg_finish(row, lane, a, bias);
    s_sum[warp][lane] = o;
    __syncthreads();

    if (threadIdx.x < 64) {
        int w0 = threadIdx.x >> 5;            // 0/1: sums vs maxes split
        int c  = threadIdx.x & 31;
        if (w0 == 0) {
            float2 S = make_float2(0.f, 0.f);
#pragma unroll
            for (int w = 0; w < 8; w++) {
                float2 v = s_sum[w][c];
                S.x += v.x; S.y += v.y;
            }
            g_psT[c * AB + blockIdx.x] = S;
        } else {
            float2 M = make_float2(0.f, 0.f);
#pragma unroll
            for (int w = 0; w < 8; w++) {
                float2 v = s_sum[w][c];
                M.x = fmaxf(M.x, v.x); M.y = fmaxf(M.y, v.y);
            }
            g_pmT[c * AB + blockIdx.x] = M;
        }
    }
}

__global__ void pool_reduce_kernel() {
    PDL_LAUNCH_DEPENDENTS();
    __shared__ float sx[256], sy[256], mx[256], my[256];
    int c   = blockIdx.x;
    int tid = threadIdx.x;
    PDL_WAIT();
    float ax = 0.f, ay = 0.f, bx = 0.f, by = 0.f;
    for (int i = tid; i < AB; i += 256) {
        float2 s = g_psT[c * AB + i];
        ax += s.x; ay += s.y;
        float2 m = g_pmT[c * AB + i];
        bx = fmaxf(bx, m.x); by = fmaxf(by, m.y);
    }
    sx[tid] = ax; sy[tid] = ay; mx[tid] = bx; my[tid] = by;
    __syncthreads();
    for (int off = 128; off > 0; off >>= 1) {
        if (tid < off) {
            sx[tid] += sx[tid + off]; sy[tid] += sy[tid + off];
            mx[tid] = fmaxf(mx[tid], mx[tid + off]);
            my[tid] = fmaxf(my[tid], my[tid + off]);
        }
        __syncthreads();
    }
    if (tid == 0) {
        g_poolS[2 * c]     = sx[0]; g_poolS[2 * c + 1] = sy[0];
        g_poolM[2 * c]     = mx[0]; g_poolM[2 * c + 1] = my[0];
    }
}

__global__ void head_kernel(const float* __restrict__ fw1,
                            const float* __restrict__ fb1,
                            const float* __restrict__ fw2,
                            const float* __restrict__ fb2,
                            float* __restrict__ out) {
    PDL_LAUNCH_DEPENDENTS();
    __shared__ float pooled[128];
    __shared__ float red[64];
    int tid = threadIdx.x;                    // 64 threads
    PDL_WAIT();
    pooled[tid]      = g_poolS[tid] * (1.0f / NN);
    pooled[tid + 64] = g_poolM[tid];
    __syncthreads();

    float acc = fb1[tid];
#pragma unroll 4
    for (int k = 0; k < 128; k++) acc = fmaf(pooled[k], fw1[k * 64 + tid], acc);
    red[tid] = fmaxf(acc, 0.f) * fw2[tid];
    __syncthreads();
    if (tid == 0) {
        float t = 0.f;
        for (int i = 0; i < 64; i++) t += red[i];
        out[0] = t + fb2[0];
    }
}

// ---------------- launcher ---------------------------------------------------
extern "C" void kernel_launch(void* const* d_in, const int* in_sizes, int n_in,
                              void* d_out, int out_size) {
    const float* x   = (const float*)d_in[0];
    const int*   ei  = (const int*)d_in[1];
    const float* W1  = (const float*)d_in[2];
    const float* b1  = (const float*)d_in[3];
    const float* W2  = (const float*)d_in[4];
    const float* b2  = (const float*)d_in[5];
    const float* W3  = (const float*)d_in[6];
    const float* b3  = (const float*)d_in[7];
    const float* fw1 = (const float*)d_in[8];
    const float* fb1 = (const float*)d_in[9];
    const float* fw2 = (const float*)d_in[10];
    const float* fb2 = (const float*)d_in[11];
    float* out = (float*)d_out;

    __half *xh, *w1t, *w2t, *w3t, *hAH;
    cudaGetSymbolAddress((void**)&xh,  g_xh);
    cudaGetSymbolAddress((void**)&w1t, g_w1t);
    cudaGetSymbolAddress((void**)&w2t, g_w2t);
    cudaGetSymbolAddress((void**)&w3t, g_w3t);
    cudaGetSymbolAddress((void**)&hAH, g_hAH);

    // host-side stream/event/attr setup (once; no device memory involved)
    static cudaStream_t sB = nullptr;
    static cudaEvent_t  eC = nullptr, eF = nullptr, eG = nullptr;
    if (sB == nullptr) {
        cudaStreamCreateWithFlags(&sB, cudaStreamNonBlocking);
        cudaEventCreateWithFlags(&eC, cudaEventDisableTiming);
        cudaEventCreateWithFlags(&eF, cudaEventDisableTiming);
        cudaEventCreateWithFlags(&eG, cudaEventDisableTiming);
        cudaFuncSetAttribute(gemm_mma_kernel<DIN>,
                             cudaFuncAttributeMaxDynamicSharedMemorySize,
                             (128 + 64) * (DIN + 8) * 2);
        cudaFuncSetAttribute(gemm_mma_kernel<HH>,
                             cudaFuncAttributeMaxDynamicSharedMemorySize,
                             (128 + 64) * (HH + 8) * 2);
    }
    const int SMEM1 = (128 + 64) * (DIN + 8) * 2;   // 52224 (K=128)
    const int SMEM2 = (128 + 64) * (HH + 8) * 2;    // 27648 (K=64)

    const int NB_N  = (NN + 255) / 256;             // 196
    const int NB_E8 = (EE / 8 + 255) / 256;         // 391
    const int NB_X  = (NN * DIN / 4 + 255) / 256;   // 6250
    const int NB_W  = (DIN * HH + 2 * HH * HH + 255) / 256;

    // PDL launch helper (main stream, programmatic serialization)
    cudaLaunchAttribute pat[1];
    pat[0].id = cudaLaunchAttributeProgrammaticStreamSerialization;
    pat[0].val.programmaticStreamSerializationAllowed = 1;
    cudaLaunchConfig_t cfg = {};
    cfg.stream = 0;
    cfg.attrs = pat;
    cfg.numAttrs = 1;
    auto LP = [&](auto kern, int g, int b, int sm, auto... as) {
        cfg.gridDim = dim3(g); cfg.blockDim = dim3(b); cfg.dynamicSmemBytes = sm;
        cudaLaunchKernelEx(&cfg, kern, as...);
    };

    // side stream: fp16 conversions run under the CSR count
    cudaEventRecord(eC, 0);
    cudaStreamWaitEvent(sB, eC, 0);
    xconv_kernel<<<NB_X, 256, 0, sB>>>(x);
    wconv_kernel<<<NB_W, 256, 0, sB>>>(W1, W2, W3);

    // main chain: count -> finish (dinv ready), PDL-linked. No init needed:
    // cursors are zero at load and re-zeroed by finish each call.
    LP(count_kernel, NB_E8, 256, 0, ei);
    LP(finish_kernel, NB_N, 256, 0);

    // fork: GEMM1 (needs dinv + converted x/W) on sB, concurrent with scatter
    cudaEventRecord(eF, 0);
    cudaStreamWaitEvent(sB, eF, 0);
    gemm_mma_kernel<DIN><<<GTB, 128, SMEM1, sB>>>((const __half*)xh, (const __half*)w1t, NN);
    cudaEventRecord(eG, sB);

    LP(scatter_kernel, NB_E8, 256, 0, ei);

    // join: agg1 needs both CSR (main/PDL) and GEMM1 (event)
    cudaStreamWaitEvent(0, eG, 0);

    LP(agg_kernel, AB, 256, 0, (const float*)b1);
    LP(gemm_mma_kernel<HH>, GTB, 128, SMEM2, (const __half*)hAH, (const __half*)w2t, NN);
    LP(agg_kernel, AB, 256, 0, (const float*)b2);
    LP(gemm_mma_kernel<HH>, GTB, 128, SMEM2, (const __half*)hAH, (const __half*)w3t, NN);
    LP(agg_pool_kernel, AB, 256, 0, (const float*)b3);
    LP(pool_reduce_kernel, 32, 256, 0);
    LP(head_kernel, 1, 64, 0, fw1, fb1, fw2, fb2, out);
}

// round 15
// speedup vs baseline: 1.0008x; 1.0008x over previous
#include <cuda_runtime.h>
#include <cuda_fp16.h>
#include <cstdint>

#define NN   50000
#define EE   800000
#define DIN  128
#define HH   64
#define AB   6250                 // agg blocks: 8 rows x 6250 = 50000 exactly
#define CW   64                   // CSR bucket capacity per node (max deg ~35)
#define GTB  391                  // gemm tile blocks: 391 x 128 rows >= NN

// ---------------- scratch (static device globals: no allocation) -------------
// Device globals are zero-initialized at module load. g_cur is re-zeroed by
// finish_kernel every call, so each launch (and每 graph replay) starts clean.
__device__ int    g_cur[NN];                 // per-node cursor (zeroed each call)
__device__ int    g_deg[NN];                 // capped degree
__device__ float  g_dinv[NN];
__device__ int    g_rank[EE];                // edge rank within dst bucket
__device__ int    g_col[(size_t)NN * CW];    // bucketed CSR; pads = NN (dummy)
__device__ __align__(16) __half g_xh[(size_t)NN * DIN];      // fp16 x
__device__ __align__(16) __half g_w1t[HH * DIN];             // W1^T [64][128] fp16
__device__ __align__(16) __half g_w2t[HH * HH];              // W2^T [64][64]
__device__ __align__(16) __half g_w3t[HH * HH];              // W3^T [64][64]
__device__ __align__(16) __half g_hH[(size_t)(NN + 1) * HH]; // gemm out: dinv*h fp16; row NN stays 0
__device__ __align__(16) __half g_hAH[(size_t)NN * HH];      // agg out fp16 (gemm2/3 input)
__device__ float2 g_psT[32 * AB];            // pool sum partials [lanecol][blk]
__device__ float2 g_pmT[32 * AB];            // pool max partials
__device__ float  g_poolS[HH];
__device__ float  g_poolM[HH];

// ---------------- PTX helpers -------------------------------------------------
__device__ __forceinline__ uint32_t smem_u32(const void* p) {
    uint32_t a;
    asm("{ .reg .u64 t; cvta.to.shared.u64 t, %1; cvt.u32.u64 %0, t; }"
        : "=r"(a) : "l"(p));
    return a;
}
__device__ __forceinline__ void ldsm4(uint32_t* r, uint32_t addr) {
    asm volatile("ldmatrix.sync.aligned.m8n8.x4.shared.b16 {%0,%1,%2,%3}, [%4];"
                 : "=r"(r[0]), "=r"(r[1]), "=r"(r[2]), "=r"(r[3]) : "r"(addr));
}
__device__ __forceinline__ void mma16816(float* c, const uint32_t* a,
                                         uint32_t b0, uint32_t b1) {
    asm volatile(
        "mma.sync.aligned.m16n8k16.row.col.f32.f16.f16.f32 "
        "{%0,%1,%2,%3}, {%4,%5,%6,%7}, {%8,%9}, {%0,%1,%2,%3};"
        : "+f"(c[0]), "+f"(c[1]), "+f"(c[2]), "+f"(c[3])
        : "r"(a[0]), "r"(a[1]), "r"(a[2]), "r"(a[3]), "r"(b0), "r"(b1));
}

// ---------------- CSR build ----------------------------------------------------
// histogram, 4 edges/thread; atomic return value = edge rank in dst bucket
__global__ void count_kernel(const int* __restrict__ ei) {
    int i = blockIdx.x * blockDim.x + threadIdx.x;
    if (i >= EE / 4) return;
    int4 d4 = reinterpret_cast<const int4*>(ei + EE)[i];
    int4 r4;
    r4.x = atomicAdd(&g_cur[d4.x], 1);
    r4.y = atomicAdd(&g_cur[d4.y], 1);
    r4.z = atomicAdd(&g_cur[d4.z], 1);
    r4.w = atomicAdd(&g_cur[d4.w], 1);
    reinterpret_cast<int4*>(g_rank)[i] = r4;
}

// dinv + capped deg + bucket pads + cursor reset (so next call starts clean)
__global__ void finish_kernel() {
    int i = blockIdx.x * blockDim.x + threadIdx.x;
    if (i >= NN) return;
    int c = g_cur[i];
    int d = min(c, CW);
    int pd = (d + 3) & ~3;
    g_deg[i]  = d;
    g_dinv[i] = rsqrtf((float)c + 1.0f);
    for (int p = d; p < pd; p++) g_col[i * CW + p] = NN;   // pad -> dummy zero row
    g_cur[i] = 0;
}

// atomic-free scatter (4 edges/thread): slot = dst*CW + rank
__global__ void scatter_kernel(const int* __restrict__ ei) {
    int i = blockIdx.x * blockDim.x + threadIdx.x;
    if (i >= EE / 4) return;
    int4 s4 = reinterpret_cast<const int4*>(ei)[i];
    int4 d4 = reinterpret_cast<const int4*>(ei + EE)[i];
    int4 r4 = reinterpret_cast<const int4*>(g_rank)[i];
    if (r4.x < CW) g_col[d4.x * CW + r4.x] = s4.x;
    if (r4.y < CW) g_col[d4.y * CW + r4.y] = s4.y;
    if (r4.z < CW) g_col[d4.z * CW + r4.z] = s4.z;
    if (r4.w < CW) g_col[d4.w * CW + r4.w] = s4.w;
}

// ---------------- fp16 conversion kernels (side stream) ----------------------
__global__ void xconv_kernel(const float* __restrict__ x) {
    int i = blockIdx.x * blockDim.x + threadIdx.x;   // over float4s: NN*DIN/4
    if (i >= NN * DIN / 4) return;
    float4 v = reinterpret_cast<const float4*>(x)[i];
    __half2 a = __floats2half2_rn(v.x, v.y);
    __half2 b = __floats2half2_rn(v.z, v.w);
    uint2 o = make_uint2(*reinterpret_cast<unsigned*>(&a), *reinterpret_cast<unsigned*>(&b));
    reinterpret_cast<uint2*>(g_xh)[i] = o;
}

__global__ void wconv_kernel(const float* __restrict__ W1,
                             const float* __restrict__ W2,
                             const float* __restrict__ W3) {
    int i = blockIdx.x * blockDim.x + threadIdx.x;
    if (i < DIN * HH) {
        int k = i / HH, n = i % HH;
        g_w1t[n * DIN + k] = __float2half(W1[i]);
    } else if (i < DIN * HH + HH * HH) {
        int j = i - DIN * HH, k = j / HH, n = j % HH;
        g_w2t[n * HH + k] = __float2half(W2[j]);
    } else if (i < DIN * HH + 2 * HH * HH) {
        int j = i - DIN * HH - HH * HH, k = j / HH, n = j % HH;
        g_w3t[n * HH + k] = __float2half(W3[j]);
    }
}

// ---------------- HMMA GEMM: hH = fp16( dinv * (A[N,K] @ Bt[64,K]^T) ) -------
// Per CTA: 128 rows x 64 cols, 4 warps (warp w = rows 32w..32w+31).
// Smem padded row stride S = K+8 halves => conflict-free ldmatrix.
template <int K>
__global__ __launch_bounds__(128) void gemm_mma_kernel(const __half* __restrict__ Asrc,
                                                       const __half* __restrict__ Bt,
                                                       int nrows) {
    constexpr int S  = K + 8;                 // halves per smem row
    constexpr int RQ = K / 8;                 // uint4 chunks per source row
    extern __shared__ __align__(16) __half smem[];
    __half* As = smem;                        // 128 x S
    __half* Bs = smem + 128 * S;              // 64 x S
    const int tid = threadIdx.x, wid = tid >> 5, lane = tid & 31;
    const int rowbase = blockIdx.x * 128;

    // fill A (guard rows past nrows with zeros)
    for (int idx = tid; idx < 128 * RQ; idx += 128) {
        int r = idx / RQ, j = idx % RQ;
        uint4 v = make_uint4(0, 0, 0, 0);
        if (rowbase + r < nrows)
            v = reinterpret_cast<const uint4*>(Asrc)[(size_t)(rowbase + r) * RQ + j];
        *reinterpret_cast<uint4*>(As + r * S + j * 8) = v;
    }
    // fill B (W^T: 64 rows x K)
    for (int idx = tid; idx < 64 * RQ; idx += 128) {
        int r = idx / RQ, j = idx % RQ;
        uint4 v = reinterpret_cast<const uint4*>(Bt)[(size_t)r * RQ + j];
        *reinterpret_cast<uint4*>(Bs + r * S + j * 8) = v;
    }
    __syncthreads();

    float acc[2][8][4];
#pragma unroll
    for (int rg = 0; rg < 2; rg++)
#pragma unroll
        for (int ng = 0; ng < 8; ng++)
#pragma unroll
            for (int q = 0; q < 4; q++) acc[rg][ng][q] = 0.f;

    const uint32_t sA = smem_u32(As), sB = smem_u32(Bs);

#pragma unroll
    for (int ks = 0; ks < K / 16; ks++) {
        uint32_t a[2][4];
#pragma unroll
        for (int rg = 0; rg < 2; rg++) {
            int row = wid * 32 + rg * 16 + (lane & 15);
            uint32_t addr = sA + (uint32_t)(row * S + ks * 16 + (lane >> 4) * 8) * 2;
            ldsm4(a[rg], addr);
        }
        uint32_t b[4][4];
#pragma unroll
        for (int np = 0; np < 4; np++) {
            int row = np * 16 + (lane & 7) + ((lane >> 4) << 3);
            int col = ks * 16 + (((lane >> 3) & 1) << 3);
            uint32_t addr = sB + (uint32_t)(row * S + col) * 2;
            ldsm4(b[np], addr);
        }
#pragma unroll
        for (int rg = 0; rg < 2; rg++)
#pragma unroll
            for (int ng = 0; ng < 8; ng++)
                mma16816(acc[rg][ng], a[rg],
                         b[ng >> 1][(ng & 1) * 2], b[ng >> 1][(ng & 1) * 2 + 1]);
    }

    // epilogue: D thread map c0,c1 -> (lane/4, 2*(lane%4)+{0,1}); c2,c3 -> row+8.
#pragma unroll
    for (int rg = 0; rg < 2; rg++) {
        int ra = rowbase + wid * 32 + rg * 16 + (lane >> 2);
        int rb = ra + 8;
        float da = (ra < nrows) ? g_dinv[ra] : 0.f;
        float db = (rb < nrows) ? g_dinv[rb] : 0.f;
#pragma unroll
        for (int ng = 0; ng < 8; ng++) {
            int col = ng * 8 + (lane & 3) * 2;
            if (ra < nrows) {
                __half2 h = __floats2half2_rn(acc[rg][ng][0] * da, acc[rg][ng][1] * da);
                *reinterpret_cast<__half2*>(g_hH + (size_t)ra * HH + col) = h;
            }
            if (rb < nrows) {
                __half2 h = __floats2half2_rn(acc[rg][ng][2] * db, acc[rg][ng][3] * db);
                *reinterpret_cast<__half2*>(g_hH + (size_t)rb * HH + col) = h;
            }
        }
    }
}

// ---------------- aggregation: warp per node, shfl-free fp16 gather ----------
// A[i] = relu( dinv_i * (sum_j h'_j + h'_i) + b ),   h' = dinv*h (fp16)
__device__ __forceinline__ float2 agg_row(int row, int lane) {
    int  deg    = g_deg[row];
    int  padded = (deg + 3) & ~3;             // pad slots index dummy zero row
    const int*      cp = g_col + row * CW;
    const unsigned* hb = reinterpret_cast<const unsigned*>(g_hH);

    float ax = 0.f, ay = 0.f;
#pragma unroll 4
    for (int p = 0; p < padded; p++) {
        int sj = __ldg(cp + p);               // warp-uniform broadcast load
        unsigned hv = __ldg(hb + sj * 32 + lane);
        float2 f = __half22float2(*reinterpret_cast<const __half2*>(&hv));
        ax += f.x;
        ay += f.y;
    }
    return make_float2(ax, ay);
}

__device__ __forceinline__ float2 agg_finish(int row, int lane, float2 a,
                                             const float* bias) {
    const unsigned* hb = reinterpret_cast<const unsigned*>(g_hH);
    unsigned hs = hb[row * 32 + lane];
    float2 fs = __half22float2(*reinterpret_cast<const __half2*>(&hs));
    float di = g_dinv[row];
    float2 b = reinterpret_cast<const float2*>(bias)[lane];
    float ox = fmaf(di, a.x + fs.x, b.x);
    float oy = fmaf(di, a.y + fs.y, b.y);
    return make_float2(fmaxf(ox, 0.f), fmaxf(oy, 0.f));
}

__global__ void agg_kernel(const float* __restrict__ bias) {
    int warp = threadIdx.x >> 5;
    int lane = threadIdx.x & 31;
    int row  = blockIdx.x * 8 + warp;
    float2 a = agg_row(row, lane);
    float2 o = agg_finish(row, lane, a, bias);
    __half2 oh = __floats2half2_rn(o.x, o.y);
    reinterpret_cast<unsigned*>(g_hAH)[row * 32 + lane] =
        *reinterpret_cast<unsigned*>(&oh);
}

// layer-3 agg with fused pooling partials (activations never materialized)
__global__ void agg_pool_kernel(const float* __restrict__ bias) {
    __shared__ float2 s_sum[8][32];
    int warp = threadIdx.x >> 5;
    int lane = threadIdx.x & 31;
    int row  = blockIdx.x * 8 + warp;

    float2 a = agg_row(row, lane);
    float2 o = agg_finish(row, lane, a, bias);
    s_sum[warp][lane] = o;
    __syncthreads();

    if (threadIdx.x < 64) {
        int w0 = threadIdx.x >> 5;            // 0/1: sums vs maxes split
        int c  = threadIdx.x & 31;
        if (w0 == 0) {
            float2 S = make_float2(0.f, 0.f);
#pragma unroll
            for (int w = 0; w < 8; w++) {
                float2 v = s_sum[w][c];
                S.x += v.x; S.y += v.y;
            }
            g_psT[c * AB + blockIdx.x] = S;
        } else {
            float2 M = make_float2(0.f, 0.f);
#pragma unroll
            for (int w = 0; w < 8; w++) {
                float2 v = s_sum[w][c];
                M.x = fmaxf(M.x, v.x); M.y = fmaxf(M.y, v.y);
            }
            g_pmT[c * AB + blockIdx.x] = M;
        }
    }
}

__global__ void pool_reduce_kernel() {
    __shared__ float sx[256], sy[256], mx[256], my[256];
    int c   = blockIdx.x;
    int tid = threadIdx.x;
    float ax = 0.f, ay = 0.f, bx = 0.f, by = 0.f;
    for (int i = tid; i < AB; i += 256) {
        float2 s = g_psT[c * AB + i];
        ax += s.x; ay += s.y;
        float2 m = g_pmT[c * AB + i];
        bx = fmaxf(bx, m.x); by = fmaxf(by, m.y);
    }
    sx[tid] = ax; sy[tid] = ay; mx[tid] = bx; my[tid] = by;
    __syncthreads();
    for (int off = 128; off > 0; off >>= 1) {
        if (tid < off) {
            sx[tid] += sx[tid + off]; sy[tid] += sy[tid + off];
            mx[tid] = fmaxf(mx[tid], mx[tid + off]);
            my[tid] = fmaxf(my[tid], my[tid + off]);
        }
        __syncthreads();
    }
    if (tid == 0) {
        g_poolS[2 * c]     = sx[0]; g_poolS[2 * c + 1] = sy[0];
        g_poolM[2 * c]     = mx[0]; g_poolM[2 * c + 1] = my[0];
    }
}

__global__ void head_kernel(const float* __restrict__ fw1,
                            const float* __restrict__ fb1,
                            const float* __restrict__ fw2,
                            const float* __restrict__ fb2,
                            float* __restrict__ out) {
    __shared__ float pooled[128];
    __shared__ float red[64];
    int tid = threadIdx.x;                    // 64 threads
    pooled[tid]      = g_poolS[tid] * (1.0f / NN);
    pooled[tid + 64] = g_poolM[tid];
    __syncthreads();

    float acc = fb1[tid];
#pragma unroll 4
    for (int k = 0; k < 128; k++) acc = fmaf(pooled[k], fw1[k * 64 + tid], acc);
    red[tid] = fmaxf(acc, 0.f) * fw2[tid];
    __syncthreads();
    if (tid == 0) {
        float t = 0.f;
        for (int i = 0; i < 64; i++) t += red[i];
        out[0] = t + fb2[0];
    }
}

// ---------------- launcher ---------------------------------------------------
extern "C" void kernel_launch(void* const* d_in, const int* in_sizes, int n_in,
                              void* d_out, int out_size) {
    const float* x   = (const float*)d_in[0];
    const int*   ei  = (const int*)d_in[1];
    const float* W1  = (const float*)d_in[2];
    const float* b1  = (const float*)d_in[3];
    const float* W2  = (const float*)d_in[4];
    const float* b2  = (const float*)d_in[5];
    const float* W3  = (const float*)d_in[6];
    const float* b3  = (const float*)d_in[7];
    const float* fw1 = (const float*)d_in[8];
    const float* fb1 = (const float*)d_in[9];
    const float* fw2 = (const float*)d_in[10];
    const float* fb2 = (const float*)d_in[11];
    float* out = (float*)d_out;

    __half *xh, *w1t, *w2t, *w3t, *hAH;
    cudaGetSymbolAddress((void**)&xh,  g_xh);
    cudaGetSymbolAddress((void**)&w1t, g_w1t);
    cudaGetSymbolAddress((void**)&w2t, g_w2t);
    cudaGetSymbolAddress((void**)&w3t, g_w3t);
    cudaGetSymbolAddress((void**)&hAH, g_hAH);

    // host-side stream/event/attr setup (once; no device memory involved)
    static cudaStream_t sB = nullptr;
    static cudaEvent_t  eC = nullptr, eF = nullptr, eG = nullptr;
    if (sB == nullptr) {
        cudaStreamCreateWithFlags(&sB, cudaStreamNonBlocking);
        cudaEventCreateWithFlags(&eC, cudaEventDisableTiming);
        cudaEventCreateWithFlags(&eF, cudaEventDisableTiming);
        cudaEventCreateWithFlags(&eG, cudaEventDisableTiming);
        cudaFuncSetAttribute(gemm_mma_kernel<DIN>,
                             cudaFuncAttributeMaxDynamicSharedMemorySize,
                             (128 + 64) * (DIN + 8) * 2);
        cudaFuncSetAttribute(gemm_mma_kernel<HH>,
                             cudaFuncAttributeMaxDynamicSharedMemorySize,
                             (128 + 64) * (HH + 8) * 2);
    }
    const int SMEM1 = (128 + 64) * (DIN + 8) * 2;   // 52224 (K=128)
    const int SMEM2 = (128 + 64) * (HH + 8) * 2;    // 27648 (K=64)

    const int NB_N  = (NN + 255) / 256;             // 196
    const int NB_E4 = (EE / 4 + 255) / 256;         // 782
    const int NB_X  = (NN * DIN / 4 + 255) / 256;   // 6250
    const int NB_W  = (DIN * HH + 2 * HH * HH + 255) / 256;

    // side stream: fp16 conversions run under the CSR count
    cudaEventRecord(eC, 0);
    cudaStreamWaitEvent(sB, eC, 0);
    xconv_kernel<<<NB_X, 256, 0, sB>>>(x);
    wconv_kernel<<<NB_W, 256, 0, sB>>>(W1, W2, W3);

    // main chain: count -> finish (dinv ready). No init needed: cursors are
    // zero at load and re-zeroed by finish every call.
    count_kernel<<<NB_E4, 256>>>(ei);
    finish_kernel<<<NB_N, 256>>>();

    // fork: GEMM1 (needs dinv + converted x/W) on sB, concurrent with scatter
    cudaEventRecord(eF, 0);
    cudaStreamWaitEvent(sB, eF, 0);
    gemm_mma_kernel<DIN><<<GTB, 128, SMEM1, sB>>>((const __half*)xh, (const __half*)w1t, NN);
    cudaEventRecord(eG, sB);

    scatter_kernel<<<NB_E4, 256>>>(ei);

    // join: agg1 needs both CSR and GEMM1
    cudaStreamWaitEvent(0, eG, 0);

    agg_kernel<<<AB, 256>>>(b1);
    gemm_mma_kernel<HH><<<GTB, 128, SMEM2>>>((const __half*)hAH, (const __half*)w2t, NN);
    agg_kernel<<<AB, 256>>>(b2);
    gemm_mma_kernel<HH><<<GTB, 128, SMEM2>>>((const __half*)hAH, (const __half*)w3t, NN);
    agg_pool_kernel<<<AB, 256>>>(b3);

    pool_reduce_kernel<<<32, 256>>>();
    head_kernel<<<1, 64>>>(fw1, fb1, fw2, fb2, out);
}

// round 16
// speedup vs baseline: 1.0707x; 1.0698x over previous
#include <cuda_runtime.h>
#include <cuda_fp16.h>
#include <cstdint>

#define NN   50000
#define EE   800000
#define DIN  128
#define HH   64
#define AB   6250                 // agg_pool blocks: 8 rows x 6250 = 50000
#define FB   3125                 // fused blocks: 16 rows x 3125 = 50000
#define CW   64                   // CSR bucket capacity per node (max deg ~35)
#define GTB  391                  // gemm tile blocks: 391 x 128 rows >= NN

// ---------------- scratch (static device globals: no allocation) -------------
// Device globals are zero-initialized at module load. g_cur is re-zeroed by
// finish_kernel every call, so each launch / graph replay starts clean.
__device__ int    g_cur[NN];                 // per-node cursor (zeroed each call)
__device__ int    g_deg[NN];                 // capped degree
__device__ float  g_dinv[NN];
__device__ int    g_rank[EE];                // edge rank within dst bucket
__device__ int    g_col[(size_t)NN * CW];    // bucketed CSR; pads = NN (dummy)
__device__ __align__(16) __half g_xh[(size_t)NN * DIN];      // fp16 x
__device__ __align__(16) __half g_w1t[HH * DIN];             // W1^T [64][128] fp16
__device__ __align__(16) __half g_w2t[HH * HH];              // W2^T [64][64]
__device__ __align__(16) __half g_w3t[HH * HH];              // W3^T [64][64]
// double-buffered h' (dinv*h, fp16); row NN stays zero (never written)
__device__ __align__(16) __half g_hA[(size_t)(NN + 1) * HH];
__device__ __align__(16) __half g_hB[(size_t)(NN + 1) * HH];
__device__ float2 g_psT[32 * AB];            // pool sum partials [lanecol][blk]
__device__ float2 g_pmT[32 * AB];            // pool max partials
__device__ float  g_poolS[HH];
__device__ float  g_poolM[HH];

// ---------------- PTX helpers -------------------------------------------------
__device__ __forceinline__ uint32_t smem_u32(const void* p) {
    uint32_t a;
    asm("{ .reg .u64 t; cvta.to.shared.u64 t, %1; cvt.u32.u64 %0, t; }"
        : "=r"(a) : "l"(p));
    return a;
}
__device__ __forceinline__ void ldsm4(uint32_t* r, uint32_t addr) {
    asm volatile("ldmatrix.sync.aligned.m8n8.x4.shared.b16 {%0,%1,%2,%3}, [%4];"
                 : "=r"(r[0]), "=r"(r[1]), "=r"(r[2]), "=r"(r[3]) : "r"(addr));
}
__device__ __forceinline__ void mma16816(float* c, const uint32_t* a,
                                         uint32_t b0, uint32_t b1) {
    asm volatile(
        "mma.sync.aligned.m16n8k16.row.col.f32.f16.f16.f32 "
        "{%0,%1,%2,%3}, {%4,%5,%6,%7}, {%8,%9}, {%0,%1,%2,%3};"
        : "+f"(c[0]), "+f"(c[1]), "+f"(c[2]), "+f"(c[3])
        : "r"(a[0]), "r"(a[1]), "r"(a[2]), "r"(a[3]), "r"(b0), "r"(b1));
}

// ---------------- CSR build ---------------------------------------------------
// histogram, 4 edges/thread; atomic return value = edge rank in dst bucket
__global__ void count_kernel(const int* __restrict__ ei) {
    int i = blockIdx.x * blockDim.x + threadIdx.x;
    if (i >= EE / 4) return;
    int4 d4 = reinterpret_cast<const int4*>(ei + EE)[i];
    int4 r4;
    r4.x = atomicAdd(&g_cur[d4.x], 1);
    r4.y = atomicAdd(&g_cur[d4.y], 1);
    r4.z = atomicAdd(&g_cur[d4.z], 1);
    r4.w = atomicAdd(&g_cur[d4.w], 1);
    reinterpret_cast<int4*>(g_rank)[i] = r4;
}

// dinv + capped deg + bucket pads + cursor reset
__global__ void finish_kernel() {
    int i = blockIdx.x * blockDim.x + threadIdx.x;
    if (i >= NN) return;
    int c = g_cur[i];
    int d = min(c, CW);
    int pd = (d + 3) & ~3;
    g_deg[i]  = d;
    g_dinv[i] = rsqrtf((float)c + 1.0f);
    for (int p = d; p < pd; p++) g_col[i * CW + p] = NN;   // pad -> dummy zero row
    g_cur[i] = 0;
}

// atomic-free scatter (4 edges/thread): slot = dst*CW + rank
__global__ void scatter_kernel(const int* __restrict__ ei) {
    int i = blockIdx.x * blockDim.x + threadIdx.x;
    if (i >= EE / 4) return;
    int4 s4 = reinterpret_cast<const int4*>(ei)[i];
    int4 d4 = reinterpret_cast<const int4*>(ei + EE)[i];
    int4 r4 = reinterpret_cast<const int4*>(g_rank)[i];
    if (r4.x < CW) g_col[d4.x * CW + r4.x] = s4.x;
    if (r4.y < CW) g_col[d4.y * CW + r4.y] = s4.y;
    if (r4.z < CW) g_col[d4.z * CW + r4.z] = s4.z;
    if (r4.w < CW) g_col[d4.w * CW + r4.w] = s4.w;
}

// ---------------- fp16 conversion kernels (side stream) ----------------------
__global__ void xconv_kernel(const float* __restrict__ x) {
    int i = blockIdx.x * blockDim.x + threadIdx.x;   // over float4s: NN*DIN/4
    if (i >= NN * DIN / 4) return;
    float4 v = reinterpret_cast<const float4*>(x)[i];
    __half2 a = __floats2half2_rn(v.x, v.y);
    __half2 b = __floats2half2_rn(v.z, v.w);
    uint2 o = make_uint2(*reinterpret_cast<unsigned*>(&a), *reinterpret_cast<unsigned*>(&b));
    reinterpret_cast<uint2*>(g_xh)[i] = o;
}

__global__ void wconv_kernel(const float* __restrict__ W1,
                             const float* __restrict__ W2,
                             const float* __restrict__ W3) {
    int i = blockIdx.x * blockDim.x + threadIdx.x;
    if (i < DIN * HH) {
        int k = i / HH, n = i % HH;
        g_w1t[n * DIN + k] = __float2half(W1[i]);
    } else if (i < DIN * HH + HH * HH) {
        int j = i - DIN * HH, k = j / HH, n = j % HH;
        g_w2t[n * HH + k] = __float2half(W2[j]);
    } else if (i < DIN * HH + 2 * HH * HH) {
        int j = i - DIN * HH - HH * HH, k = j / HH, n = j % HH;
        g_w3t[n * HH + k] = __float2half(W3[j]);
    }
}

// ---------------- GEMM1 (HMMA): hout = fp16( dinv * (A[N,128] @ Bt^T) ) ------
// Per CTA: 128 rows x 64 cols, 4 warps. Smem row stride S=K+8 (conflict-free).
template <int K>
__global__ __launch_bounds__(128) void gemm_mma_kernel(const __half* __restrict__ Asrc,
                                                       const __half* __restrict__ Bt,
                                                       __half* __restrict__ hout,
                                                       int nrows) {
    constexpr int S  = K + 8;
    constexpr int RQ = K / 8;
    extern __shared__ __align__(16) __half smem[];
    __half* As = smem;                        // 128 x S
    __half* Bs = smem + 128 * S;              // 64 x S
    const int tid = threadIdx.x, wid = tid >> 5, lane = tid & 31;
    const int rowbase = blockIdx.x * 128;

    for (int idx = tid; idx < 128 * RQ; idx += 128) {
        int r = idx / RQ, j = idx % RQ;
        uint4 v = make_uint4(0, 0, 0, 0);
        if (rowbase + r < nrows)
            v = reinterpret_cast<const uint4*>(Asrc)[(size_t)(rowbase + r) * RQ + j];
        *reinterpret_cast<uint4*>(As + r * S + j * 8) = v;
    }
    for (int idx = tid; idx < 64 * RQ; idx += 128) {
        int r = idx / RQ, j = idx % RQ;
        uint4 v = reinterpret_cast<const uint4*>(Bt)[(size_t)r * RQ + j];
        *reinterpret_cast<uint4*>(Bs + r * S + j * 8) = v;
    }
    __syncthreads();

    float acc[2][8][4];
#pragma unroll
    for (int rg = 0; rg < 2; rg++)
#pragma unroll
        for (int ng = 0; ng < 8; ng++)
#pragma unroll
            for (int q = 0; q < 4; q++) acc[rg][ng][q] = 0.f;

    const uint32_t sA = smem_u32(As), sB = smem_u32(Bs);

#pragma unroll
    for (int ks = 0; ks < K / 16; ks++) {
        uint32_t a[2][4];
#pragma unroll
        for (int rg = 0; rg < 2; rg++) {
            int row = wid * 32 + rg * 16 + (lane & 15);
            ldsm4(a[rg], sA + (uint32_t)(row * S + ks * 16 + (lane >> 4) * 8) * 2);
        }
        uint32_t b[4][4];
#pragma unroll
        for (int np = 0; np < 4; np++) {
            int row = np * 16 + (lane & 7) + ((lane >> 4) << 3);
            int col = ks * 16 + (((lane >> 3) & 1) << 3);
            ldsm4(b[np], sB + (uint32_t)(row * S + col) * 2);
        }
#pragma unroll
        for (int rg = 0; rg < 2; rg++)
#pragma unroll
            for (int ng = 0; ng < 8; ng++)
                mma16816(acc[rg][ng], a[rg],
                         b[ng >> 1][(ng & 1) * 2], b[ng >> 1][(ng & 1) * 2 + 1]);
    }

#pragma unroll
    for (int rg = 0; rg < 2; rg++) {
        int ra = rowbase + wid * 32 + rg * 16 + (lane >> 2);
        int rb = ra + 8;
        float da = (ra < nrows) ? g_dinv[ra] : 0.f;
        float db = (rb < nrows) ? g_dinv[rb] : 0.f;
#pragma unroll
        for (int ng = 0; ng < 8; ng++) {
            int col = ng * 8 + (lane & 3) * 2;
            if (ra < nrows) {
                __half2 h = __floats2half2_rn(acc[rg][ng][0] * da, acc[rg][ng][1] * da);
                *reinterpret_cast<__half2*>(hout + (size_t)ra * HH + col) = h;
            }
            if (rb < nrows) {
                __half2 h = __floats2half2_rn(acc[rg][ng][2] * db, acc[rg][ng][3] * db);
                *reinterpret_cast<__half2*>(hout + (size_t)rb * HH + col) = h;
            }
        }
    }
}

// ---------------- aggregation core (warp per node, int4 col broadcast) -------
__device__ __forceinline__ float2 agg_row(const __half* hin, int row, int lane) {
    int  deg = g_deg[row];
    int  nq  = (deg + 3) >> 2;                // bucket padded to mult of 4
    const int4*     cp = reinterpret_cast<const int4*>(g_col + row * CW);
    const unsigned* hb = reinterpret_cast<const unsigned*>(hin);

    float ax = 0.f, ay = 0.f;
    for (int q = 0; q < nq; q++) {
        int4 c4 = __ldg(cp + q);              // one broadcast per 4 edges
        unsigned h0 = __ldg(hb + c4.x * 32 + lane);
        unsigned h1 = __ldg(hb + c4.y * 32 + lane);
        unsigned h2 = __ldg(hb + c4.z * 32 + lane);
        unsigned h3 = __ldg(hb + c4.w * 32 + lane);
        float2 f0 = __half22float2(*reinterpret_cast<const __half2*>(&h0));
        float2 f1 = __half22float2(*reinterpret_cast<const __half2*>(&h1));
        float2 f2 = __half22float2(*reinterpret_cast<const __half2*>(&h2));
        float2 f3 = __half22float2(*reinterpret_cast<const __half2*>(&h3));
        ax += (f0.x + f1.x) + (f2.x + f3.x);
        ay += (f0.y + f1.y) + (f2.y + f3.y);
    }
    return make_float2(ax, ay);
}

__device__ __forceinline__ float2 agg_finish(const __half* hin, int row, int lane,
                                             float2 a, const float* bias) {
    const unsigned* hb = reinterpret_cast<const unsigned*>(hin);
    unsigned hs = hb[row * 32 + lane];
    float2 fs = __half22float2(*reinterpret_cast<const __half2*>(&hs));
    float di = g_dinv[row];
    float2 b = reinterpret_cast<const float2*>(bias)[lane];
    float ox = fmaf(di, a.x + fs.x, b.x);
    float oy = fmaf(di, a.y + fs.y, b.y);
    return make_float2(fmaxf(ox, 0.f), fmaxf(oy, 0.f));
}

// ---------------- fused agg + next-layer GEMM --------------------------------
// 16 warps: warp w aggs row (blk*16+w) -> relu(a) into smem (fp16).
// Then warps 0-3 compute hout = fp16( dinv * (a[16,64] @ Wt[64,64]^T) ) via
// HMMA (warp w covers output cols 16w..16w+15). Writes a DIFFERENT buffer
// than it gathers from (double-buffered hH), so no cross-block races.
__global__ __launch_bounds__(512) void agg_gemm_kernel(const __half* __restrict__ hin,
                                                       const float* __restrict__ bias,
                                                       const __half* __restrict__ Wt,
                                                       __half* __restrict__ hout) {
    constexpr int S = HH + 8;                 // 72 halves: conflict-free ldsm
    __shared__ __align__(16) __half a_s[16 * S];
    __shared__ __align__(16) __half b_s[64 * S];
    const int tid = threadIdx.x, wid = tid >> 5, lane = tid & 31;
    const int rowbase = blockIdx.x * 16;
    const int row = rowbase + wid;

    // load W tile: 64 rows x 8 uint4 = 512 loads, one per thread
    {
        int r = tid >> 3, j = tid & 7;
        uint4 v = reinterpret_cast<const uint4*>(Wt)[r * 8 + j];
        *reinterpret_cast<uint4*>(b_s + r * S + j * 8) = v;
    }

    // aggregate this warp's row, stage fp16 activations
    float2 a = agg_row(hin, row, lane);
    float2 o = agg_finish(hin, row, lane, a, bias);
    __half2 oh = __floats2half2_rn(o.x, o.y);
    *reinterpret_cast<__half2*>(a_s + wid * S + lane * 2) = oh;
    __syncthreads();
    if (wid >= 4) return;

    float acc[2][4];
#pragma unroll
    for (int ng = 0; ng < 2; ng++)
#pragma unroll
        for (int q = 0; q < 4; q++) acc[ng][q] = 0.f;

    const uint32_t sA = smem_u32(a_s), sB = smem_u32(b_s);
#pragma unroll
    for (int ks = 0; ks < 4; ks++) {
        uint32_t a4[4];
        ldsm4(a4, sA + (uint32_t)((lane & 15) * S + ks * 16 + (lane >> 4) * 8) * 2);
        uint32_t b4[4];
        int rowb = wid * 16 + (lane & 7) + ((lane >> 4) << 3);
        int colb = ks * 16 + (((lane >> 3) & 1) << 3);
        ldsm4(b4, sB + (uint32_t)(rowb * S + colb) * 2);
        mma16816(acc[0], a4, b4[0], b4[1]);
        mma16816(acc[1], a4, b4[2], b4[3]);
    }

    // epilogue: rows ra=rowbase+lane/4, rb=ra+8; cols 16*wid + ng*8 + 2*(lane%4)
    int ra = rowbase + (lane >> 2);
    int rb = ra + 8;
    float da = g_dinv[ra], db = g_dinv[rb];
#pragma unroll
    for (int ng = 0; ng < 2; ng++) {
        int col = wid * 16 + ng * 8 + (lane & 3) * 2;
        __half2 h0 = __floats2half2_rn(acc[ng][0] * da, acc[ng][1] * da);
        *reinterpret_cast<__half2*>(hout + (size_t)ra * HH + col) = h0;
        __half2 h1 = __floats2half2_rn(acc[ng][2] * db, acc[ng][3] * db);
        *reinterpret_cast<__half2*>(hout + (size_t)rb * HH + col) = h1;
    }
}

// layer-3 agg with fused pooling partials (activations never materialized)
__global__ void agg_pool_kernel(const __half* __restrict__ hin,
                                const float* __restrict__ bias) {
    __shared__ float2 s_sum[8][32];
    int warp = threadIdx.x >> 5;
    int lane = threadIdx.x & 31;
    int row  = blockIdx.x * 8 + warp;

    float2 a = agg_row(hin, row, lane);
    float2 o = agg_finish(hin, row, lane, a, bias);
    s_sum[warp][lane] = o;
    __syncthreads();

    if (threadIdx.x < 64) {
        int w0 = threadIdx.x >> 5;            // 0/1: sums vs maxes split
        int c  = threadIdx.x & 31;
        if (w0 == 0) {
            float2 S = make_float2(0.f, 0.f);
#pragma unroll
            for (int w = 0; w < 8; w++) {
                float2 v = s_sum[w][c];
                S.x += v.x; S.y += v.y;
            }
            g_psT[c * AB + blockIdx.x] = S;
        } else {
            float2 M = make_float2(0.f, 0.f);
#pragma unroll
            for (int w = 0; w < 8; w++) {
                float2 v = s_sum[w][c];
                M.x = fmaxf(M.x, v.x); M.y = fmaxf(M.y, v.y);
            }
            g_pmT[c * AB + blockIdx.x] = M;
        }
    }
}

__global__ void pool_reduce_kernel() {
    __shared__ float sx[256], sy[256], mx[256], my[256];
    int c   = blockIdx.x;
    int tid = threadIdx.x;
    float ax = 0.f, ay = 0.f, bx = 0.f, by = 0.f;
    for (int i = tid; i < AB; i += 256) {
        float2 s = g_psT[c * AB + i];
        ax += s.x; ay += s.y;
        float2 m = g_pmT[c * AB + i];
        bx = fmaxf(bx, m.x); by = fmaxf(by, m.y);
    }
    sx[tid] = ax; sy[tid] = ay; mx[tid] = bx; my[tid] = by;
    __syncthreads();
    for (int off = 128; off > 0; off >>= 1) {
        if (tid < off) {
            sx[tid] += sx[tid + off]; sy[tid] += sy[tid + off];
            mx[tid] = fmaxf(mx[tid], mx[tid + off]);
            my[tid] = fmaxf(my[tid], my[tid + off]);
        }
        __syncthreads();
    }
    if (tid == 0) {
        g_poolS[2 * c]     = sx[0]; g_poolS[2 * c + 1] = sy[0];
        g_poolM[2 * c]     = mx[0]; g_poolM[2 * c + 1] = my[0];
    }
}

__global__ void head_kernel(const float* __restrict__ fw1,
                            const float* __restrict__ fb1,
                            const float* __restrict__ fw2,
                            const float* __restrict__ fb2,
                            float* __restrict__ out) {
    __shared__ float pooled[128];
    __shared__ float red[64];
    int tid = threadIdx.x;                    // 64 threads
    pooled[tid]      = g_poolS[tid] * (1.0f / NN);
    pooled[tid + 64] = g_poolM[tid];
    __syncthreads();

    float acc = fb1[tid];
#pragma unroll 4
    for (int k = 0; k < 128; k++) acc = fmaf(pooled[k], fw1[k * 64 + tid], acc);
    red[tid] = fmaxf(acc, 0.f) * fw2[tid];
    __syncthreads();
    if (tid == 0) {
        float t = 0.f;
        for (int i = 0; i < 64; i++) t += red[i];
        out[0] = t + fb2[0];
    }
}

// ---------------- launcher ---------------------------------------------------
extern "C" void kernel_launch(void* const* d_in, const int* in_sizes, int n_in,
                              void* d_out, int out_size) {
    const float* x   = (const float*)d_in[0];
    const int*   ei  = (const int*)d_in[1];
    const float* W1  = (const float*)d_in[2];
    const float* b1  = (const float*)d_in[3];
    const float* W2  = (const float*)d_in[4];
    const float* b2  = (const float*)d_in[5];
    const float* W3  = (const float*)d_in[6];
    const float* b3  = (const float*)d_in[7];
    const float* fw1 = (const float*)d_in[8];
    const float* fb1 = (const float*)d_in[9];
    const float* fw2 = (const float*)d_in[10];
    const float* fb2 = (const float*)d_in[11];
    float* out = (float*)d_out;

    __half *xh, *w1t, *w2t, *w3t, *hA, *hB;
    cudaGetSymbolAddress((void**)&xh,  g_xh);
    cudaGetSymbolAddress((void**)&w1t, g_w1t);
    cudaGetSymbolAddress((void**)&w2t, g_w2t);
    cudaGetSymbolAddress((void**)&w3t, g_w3t);
    cudaGetSymbolAddress((void**)&hA,  g_hA);
    cudaGetSymbolAddress((void**)&hB,  g_hB);

    // host-side stream/event/attr setup (once; no device memory involved)
    static cudaStream_t sB = nullptr;
    static cudaEvent_t  eC = nullptr, eF = nullptr, eG = nullptr;
    if (sB == nullptr) {
        cudaStreamCreateWithFlags(&sB, cudaStreamNonBlocking);
        cudaEventCreateWithFlags(&eC, cudaEventDisableTiming);
        cudaEventCreateWithFlags(&eF, cudaEventDisableTiming);
        cudaEventCreateWithFlags(&eG, cudaEventDisableTiming);
        cudaFuncSetAttribute(gemm_mma_kernel<DIN>,
                             cudaFuncAttributeMaxDynamicSharedMemorySize,
                             (128 + 64) * (DIN + 8) * 2);
    }
    const int SMEM1 = (128 + 64) * (DIN + 8) * 2;   // 52224 (K=128)

    const int NB_N  = (NN + 255) / 256;             // 196
    const int NB_E4 = (EE / 4 + 255) / 256;         // 782
    const int NB_X  = (NN * DIN / 4 + 255) / 256;   // 6250
    const int NB_W  = (DIN * HH + 2 * HH * HH + 255) / 256;

    // side stream: fp16 conversions run under the CSR count
    cudaEventRecord(eC, 0);
    cudaStreamWaitEvent(sB, eC, 0);
    xconv_kernel<<<NB_X, 256, 0, sB>>>(x);
    wconv_kernel<<<NB_W, 256, 0, sB>>>(W1, W2, W3);

    // main chain: count -> finish (dinv ready). No init needed: cursors are
    // zero at load and re-zeroed by finish every call.
    count_kernel<<<NB_E4, 256>>>(ei);
    finish_kernel<<<NB_N, 256>>>();

    // fork: GEMM1 (needs dinv + converted x/W) on sB, concurrent with scatter
    cudaEventRecord(eF, 0);
    cudaStreamWaitEvent(sB, eF, 0);
    gemm_mma_kernel<DIN><<<GTB, 128, SMEM1, sB>>>((const __half*)xh, (const __half*)w1t,
                                                  hA, NN);
    cudaEventRecord(eG, sB);

    scatter_kernel<<<NB_E4, 256>>>(ei);

    // join: fused layer 1 needs both CSR and GEMM1
    cudaStreamWaitEvent(0, eG, 0);

    // fused agg+GEMM layers (double-buffered h')
    agg_gemm_kernel<<<FB, 512>>>(hA, b1, w2t, hB);   // agg1 + gemm2
    agg_gemm_kernel<<<FB, 512>>>(hB, b2, w3t, hA);   // agg2 + gemm3
    agg_pool_kernel<<<AB, 256>>>(hA, b3);            // agg3 + pooling partials

    pool_reduce_kernel<<<32, 256>>>();
    head_kernel<<<1, 64>>>(fw1, fb1, fw2, fb2, out);
}